// round 7
// baseline (speedup 1.0000x reference)
#include <cuda_runtime.h>
#include <math.h>

// Fixed shapes: B=32, S=128, V=8, T=66 -> 256 independent sequences.
// TWO sequences per block (chains interleaved between the same barriers).
// 136 threads; work slot = (column, row-half): col = tid>>1, half = tid&1.
#define TT   66
#define SS   128
#define NSEQ 256
#define NBLK 128
#define NTHR 136
#define NW   5
#define USTR 72          // u ping-pong stride (floats)

typedef unsigned long long ull;

__device__ float        g_partial[NSEQ];
__device__ unsigned int g_count = 0;

static __device__ __forceinline__ ull pk2(float lo, float hi) {
    ull r; asm("mov.b64 %0, {%1,%2};" : "=l"(r) : "f"(lo), "f"(hi)); return r;
}
static __device__ __forceinline__ void fma2(ull& d, ull a, ull b) {
    asm("fma.rn.f32x2 %0, %1, %2, %0;" : "+l"(d) : "l"(a), "l"(b));
}
static __device__ __forceinline__ void add2(ull& d, ull a, ull b) {
    asm("add.rn.f32x2 %0, %1, %2;" : "=l"(d) : "l"(a), "l"(b));
}
static __device__ __forceinline__ float2 upk2(ull v) {
    float lo, hi; asm("mov.b64 {%0,%1}, %2;" : "=f"(lo), "=f"(hi) : "l"(v));
    return make_float2(lo, hi);
}

// u slab layout (USTR floats): [0..31]=u0..31, [36..67]=u32..63 (bank shift),
// [68..69]=u64,u65. Writer loc for col c: c + (c>=32 ? 4 : 0).
#define SMEM_FLOATS (2*SS*TT + 4*USTR + 8*NW + 4)
#define SMEM_BYTES  (SMEM_FLOATS*4)

__global__ void __launch_bounds__(NTHR) crf_kernel(
    const float* __restrict__ score,       // [B,S,S,T]
    const float* __restrict__ trans,       // [T,T]
    const float* __restrict__ startT,      // [T]
    const float* __restrict__ endT,        // [T]
    const int*   __restrict__ v_label,     // [B*V]
    const int*   __restrict__ role_label,  // [B*V][S]
    float*       __restrict__ out)
{
    extern __shared__ __align__(16) float sm[];
    float* esh0  = sm;                     // [SS][TT] exp(emissions) seq0
    float* esh1  = sm + SS*TT;             // seq1
    float* ubA   = esh1 + SS*TT;           // [2][USTR] ping-pong, seq0
    float* ubB   = ubA + 2*USTR;           // [2][USTR] seq1
    float* wmax0 = ubB + 2*USTR;           // [NW]
    float* wmax1 = wmax0 + NW;             // [NW]
    float* sg0   = wmax1 + NW;             // [NW]
    float* sg1   = sg0 + NW;               // [NW]
    float* sws   = sg1 + NW;               // [2*NW]
    float* wred  = sws + 2*NW;             // [NW]
    int*   sflag = (int*)(wred + NW);

    const int tid  = threadIdx.x;
    const int lane = tid & 31;
    const int wid  = tid >> 5;
    const int s0   = blockIdx.x*2;
    const int s1   = s0 + 1;
    const float* erow0 = score + ((size_t)((s0 >> 3)*SS + __ldg(&v_label[s0])))*SS*TT;
    const float* erow1 = score + ((size_t)((s1 >> 3)*SS + __ldg(&v_label[s1])))*SS*TT;

    const bool act = (tid < 132);
    const int  cc  = act ? (tid >> 1) : 0;
    const int  h   = tid & 1;
    const int  loc = cc + ((cc >= 32) ? 4 : 0);

    // ---- gold paths (one position per thread, both seqs) ----
    float g0 = 0.f, g1 = 0.f;
    if (tid < 128) {
        int s = tid;
        {
            int tg = __ldg(&role_label[s0*SS + s]);
            g0 = __ldg(&erow0[s*TT + tg]);
            if (s < SS-1) g0 += __ldg(&trans[tg*TT + __ldg(&role_label[s0*SS + s + 1])]);
            else          g0 += __ldg(&endT[tg]);
            if (s == 0)   g0 += __ldg(&startT[tg]);
        }
        {
            int tg = __ldg(&role_label[s1*SS + s]);
            g1 = __ldg(&erow1[s*TT + tg]);
            if (s < SS-1) g1 += __ldg(&trans[tg*TT + __ldg(&role_label[s1*SS + s + 1])]);
            else          g1 += __ldg(&endT[tg]);
            if (s == 0)   g1 += __ldg(&startT[tg]);
        }
    }
    #pragma unroll
    for (int o = 16; o; o >>= 1) {
        g0 += __shfl_xor_sync(~0u, g0, o);
        g1 += __shfl_xor_sync(~0u, g1, o);
    }
    if (lane == 0) { sg0[wid] = g0; sg1[wid] = g1; }

    // ---- prologue: exp(emissions) into smem for both seqs ----
    {
        const float4* sA = (const float4*)erow0;
        const float4* sB = (const float4*)erow1;
        float4* dA = (float4*)esh0;
        float4* dB = (float4*)esh1;
        #pragma unroll 4
        for (int k = tid; k < (SS*TT)/4; k += NTHR) {
            float4 va = __ldg(&sA[k]);
            float4 vb = __ldg(&sB[k]);
            va.x = __expf(va.x); va.y = __expf(va.y); va.z = __expf(va.z); va.w = __expf(va.w);
            vb.x = __expf(vb.x); vb.y = __expf(vb.y); vb.z = __expf(vb.z); vb.w = __expf(vb.w);
            dA[k] = va;
            dB[k] = vb;
        }
    }

    // ---- exp(trans) rows for my (col, half) — shared by both sequences ----
    ull e[17];
    if (act) {
        #pragma unroll
        for (int k = 0; k < 16; k++) {
            int rr = h*32 + 2*k;
            e[k] = pk2(__expf(__ldg(&trans[rr*TT + cc])),
                       __expf(__ldg(&trans[(rr+1)*TT + cc])));
        }
        e[16] = (h == 0) ? pk2(__expf(__ldg(&trans[64*TT + cc])),
                               __expf(__ldg(&trans[65*TT + cc]))) : 0ULL;
    } else {
        #pragma unroll
        for (int k = 0; k < 17; k++) e[k] = 0ULL;
    }
    const float eE = (act && h == 0) ? __expf(__ldg(&endT[cc])) : 0.f;
    const float st = act ? __expf(__ldg(&startT[cc])) : 0.f;

    __syncthreads();   // esh ready

    // ---- u0 = exp(start) * expEmis[0]; initial per-seq renorm ----
    float r0 = act ? (st * esh0[cc]) : 0.f;
    float r1 = act ? (st * esh1[cc]) : 0.f;
    if (act && h == 0) { ubA[loc] = r0; ubB[loc] = r1; }
    {
        float m0 = r0, m1 = r1;
        #pragma unroll
        for (int o = 16; o; o >>= 1) {
            m0 = fmaxf(m0, __shfl_xor_sync(~0u, m0, o));
            m1 = fmaxf(m1, __shfl_xor_sync(~0u, m1, o));
        }
        if (lane == 0) { wmax0[wid] = m0; wmax1[wid] = m1; }
    }
    __syncthreads();
    float mA  = fmaxf(fmaxf(fmaxf(wmax0[0], wmax0[1]), fmaxf(wmax0[2], wmax0[3])), wmax0[4]);
    float mB  = fmaxf(fmaxf(fmaxf(wmax1[0], wmax1[1]), fmaxf(wmax1[2], wmax1[3])), wmax1[4]);
    float scA = __fdividef(1.0f, mA);
    float scB = __fdividef(1.0f, mB);
    float LA  = __logf(mA);
    float LB  = __logf(mB);

    // ---- one step advancing BOTH sequences (independent chains overlap) ----
    auto STEP2 = [&](int t, const float* ucA, float* unA,
                            const float* ucB, float* unB,
                            float sA2, float sB2, bool renorm) {
        float emA = esh0[t*TT + cc];
        float emB = esh1[t*TT + cc];
        const ulonglong2* a2 = (const ulonglong2*)(ucA + h*36);
        const ulonglong2* b2 = (const ulonglong2*)(ucB + h*36);
        ull dA0 = 0, dA1 = 0, dB0 = 0, dB1 = 0;
        #pragma unroll
        for (int i = 0; i < 8; i++) {
            ulonglong2 va = a2[i];
            ulonglong2 vb = b2[i];
            fma2(dA0, va.x, e[2*i]);   fma2(dB0, vb.x, e[2*i]);
            fma2(dA1, va.y, e[2*i+1]); fma2(dB1, vb.y, e[2*i+1]);
        }
        ull lastA = *(const ull*)(ucA + 68);
        ull lastB = *(const ull*)(ucB + 68);
        fma2(dA0, lastA, e[16]);
        fma2(dB0, lastB, e[16]);
        add2(dA0, dA0, dA1);
        add2(dB0, dB0, dB1);
        float2 fA = upk2(dA0), fB = upk2(dB0);
        float vA = fA.x + fA.y;
        float vB = fB.x + fB.y;
        vA += __shfl_xor_sync(~0u, vA, 1);
        vB += __shfl_xor_sync(~0u, vB, 1);
        r0 = act ? vA * (sA2 * emA) : 0.f;
        r1 = act ? vB * (sB2 * emB) : 0.f;
        if (act && h == 0) { unA[loc] = r0; unB[loc] = r1; }
        if (renorm) {
            float m0 = r0, m1 = r1;
            #pragma unroll
            for (int o = 16; o; o >>= 1) {
                m0 = fmaxf(m0, __shfl_xor_sync(~0u, m0, o));
                m1 = fmaxf(m1, __shfl_xor_sync(~0u, m1, o));
            }
            if (lane == 0) { wmax0[wid] = m0; wmax1[wid] = m1; }
        }
        __syncthreads();
    };

    // ---- main scan: 15 groups of 8 + 7-step tail; renorm at group ends ----
    float* ucA = ubA; float* unA = ubA + USTR;
    float* ucB = ubB; float* unB = ubB + USTR;
    int t = 1;
    for (int grp = 0; grp < 16; grp++) {
        const int nsteps = (grp == 15) ? 7 : 8;
        #pragma unroll 8
        for (int q = 0; q < nsteps; q++) {
            STEP2(t, ucA, unA, ucB, unB,
                  (q == 0) ? scA : 1.0f, (q == 0) ? scB : 1.0f,
                  (q == nsteps-1) && (grp < 15));
            float* tp;
            tp = ucA; ucA = unA; unA = tp;
            tp = ucB; ucB = unB; unB = tp;
            t++;
        }
        if (grp < 15) {
            mA  = fmaxf(fmaxf(fmaxf(wmax0[0], wmax0[1]), fmaxf(wmax0[2], wmax0[3])), wmax0[4]);
            mB  = fmaxf(fmaxf(fmaxf(wmax1[0], wmax1[1]), fmaxf(wmax1[2], wmax1[3])), wmax1[4]);
            scA = __fdividef(1.0f, mA);
            scB = __fdividef(1.0f, mB);
            LA += __logf(mA);
            LB += __logf(mB);
        }
    }

    // ---- epilogue: logZ per sequence ----
    float cA = r0 * eE;    // h==1 / idle threads: eE = 0
    float cB = r1 * eE;
    #pragma unroll
    for (int o = 16; o; o >>= 1) {
        cA += __shfl_xor_sync(~0u, cA, o);
        cB += __shfl_xor_sync(~0u, cB, o);
    }
    if (lane == 0) { sws[wid] = cA; sws[NW + wid] = cB; }
    __syncthreads();

    if (tid == 0) {
        float wsA = (((sws[0] + sws[1]) + (sws[2] + sws[3])) + sws[4]);
        float wsB = (((sws[5] + sws[6]) + (sws[7] + sws[8])) + sws[9]);
        float gA  = (((sg0[0] + sg0[1]) + (sg0[2] + sg0[3])) + sg0[4]);
        float gB  = (((sg1[0] + sg1[1]) + (sg1[2] + sg1[3])) + sg1[4]);
        __stcg(&g_partial[s0], __logf(wsA) + LA - gA);
        __stcg(&g_partial[s1], __logf(wsB) + LB - gB);
        __threadfence();
        unsigned c0 = atomicAdd(&g_count, 1u);
        *sflag = (c0 == NBLK - 1) ? 1 : 0;
    }
    __syncthreads();

    // ---- fused final reduction in the last block ----
    if (*sflag) {
        float v = 0.f;
        if (tid < 128) v = __ldcg(&g_partial[tid]) + __ldcg(&g_partial[tid + 128]);
        #pragma unroll
        for (int o = 16; o; o >>= 1) v += __shfl_xor_sync(~0u, v, o);
        if (lane == 0) wred[wid] = v;
        __syncthreads();
        if (tid == 0) {
            out[0] = (((wred[0] + wred[1]) + (wred[2] + wred[3])) + wred[4])
                     * (1.0f / (float)NSEQ);
            g_count = 0;                       // reset for next graph replay
        }
    }
}

extern "C" void kernel_launch(void* const* d_in, const int* in_sizes, int n_in,
                              void* d_out, int out_size) {
    const float* score      = (const float*)d_in[0];
    const float* trans      = (const float*)d_in[1];
    const float* startT     = (const float*)d_in[2];
    const float* endT       = (const float*)d_in[3];
    const int*   v_label    = (const int*)d_in[4];
    const int*   role_label = (const int*)d_in[5];
    float* out = (float*)d_out;

    cudaFuncSetAttribute(crf_kernel,
                         cudaFuncAttributeMaxDynamicSharedMemorySize, SMEM_BYTES);

    crf_kernel<<<NBLK, NTHR, SMEM_BYTES>>>(
        score, trans, startT, endT, v_label, role_label, out);
}

// round 8
// speedup vs baseline: 1.2613x; 1.2613x over previous
#include <cuda_runtime.h>
#include <math.h>

// Fixed shapes: B=32, S=128, V=8, T=66 -> 256 independent sequences.
// One block per sequence. Bidirectional scan: forward alpha (t=1..63) and
// backward w (t=126..64) advance together in each barrier interval -> serial
// depth 64 instead of 127. Slot = (column, half): col = tid>>1, half = tid&1.
#define TT   66
#define SS   128
#define NSEQ 256
#define NTHR 160          // 5 FULL warps (132 active slots + padding)
#define NW   5
#define USTR 72           // u ping-pong stride (floats)

typedef unsigned long long ull;

__device__ float        g_partial[NSEQ];
__device__ unsigned int g_count = 0;

static __device__ __forceinline__ ull pk2(float lo, float hi) {
    ull r; asm("mov.b64 %0, {%1,%2};" : "=l"(r) : "f"(lo), "f"(hi)); return r;
}
static __device__ __forceinline__ void fma2(ull& d, ull a, ull b) {
    asm("fma.rn.f32x2 %0, %1, %2, %0;" : "+l"(d) : "l"(a), "l"(b));
}
static __device__ __forceinline__ void add2(ull& d, ull a, ull b) {
    asm("add.rn.f32x2 %0, %1, %2;" : "=l"(d) : "l"(a), "l"(b));
}
static __device__ __forceinline__ float2 upk2(ull v) {
    float lo, hi; asm("mov.b64 {%0,%1}, %2;" : "=f"(lo), "=f"(hi) : "l"(v));
    return make_float2(lo, hi);
}

// u slab (USTR floats): [0..31]=u0..31, [36..67]=u32..63 (bank shift), [68..69]=u64,u65
#define SMEM_FLOATS (SS*TT + 4*USTR + 6*NW + 4)
#define SMEM_BYTES  (SMEM_FLOATS*4)

__global__ void __launch_bounds__(NTHR) crf_kernel(
    const float* __restrict__ score,       // [B,S,S,T]
    const float* __restrict__ trans,       // [T,T]
    const float* __restrict__ startT,      // [T]
    const float* __restrict__ endT,        // [T]
    const int*   __restrict__ v_label,     // [B*V]
    const int*   __restrict__ role_label,  // [B*V][S]
    float*       __restrict__ out)
{
    extern __shared__ __align__(16) float sm[];
    float* esh   = sm;                     // [SS][TT] exp(emissions)
    float* uF    = sm + SS*TT;             // [2][USTR] forward alpha
    float* uW    = uF + 2*USTR;            // [2][USTR] backward w
    float* wmaxF = uW + 2*USTR;            // [NW]
    float* wmaxB = wmaxF + NW;             // [NW]
    float* sgold = wmaxB + NW;             // [NW]
    float* sws   = sgold + NW;             // [NW]
    float* wred  = sws + NW;               // [NW]
    float* wpad  = wred + NW;              // [NW] (spare)
    int*   sflag = (int*)(wpad + NW);

    const int tid  = threadIdx.x;
    const int lane = tid & 31;
    const int wid  = tid >> 5;
    const int seq  = blockIdx.x;
    const int b    = seq >> 3;             // V = 8
    const int vr   = __ldg(&v_label[seq]);
    const float* erow = score + ((size_t)(b*SS + vr))*SS*TT;

    const bool act = (tid < 132);
    const int  cc  = act ? (tid >> 1) : 0;
    const int  h   = tid & 1;
    const int  loc = cc + ((cc >= 32) ? 4 : 0);

    // ---- gold path: one position per thread (tid < 128) ----
    float gold = 0.f;
    if (tid < 128) {
        int s  = tid;
        int tg = __ldg(&role_label[seq*SS + s]);
        gold = __ldg(&erow[s*TT + tg]);
        if (s < SS-1) gold += __ldg(&trans[tg*TT + __ldg(&role_label[seq*SS + s + 1])]);
        else          gold += __ldg(&endT[tg]);
        if (s == 0)   gold += __ldg(&startT[tg]);
    }
    #pragma unroll
    for (int o = 16; o; o >>= 1) gold += __shfl_xor_sync(~0u, gold, o);
    if (lane == 0) sgold[wid] = gold;

    // ---- prologue: exp(emissions) into smem ----
    {
        const float4* src = (const float4*)erow;
        float4*       dst = (float4*)esh;
        #pragma unroll 4
        for (int k = tid; k < (SS*TT)/4; k += NTHR) {
            float4 v = __ldg(&src[k]);
            v.x = __expf(v.x); v.y = __expf(v.y);
            v.z = __expf(v.z); v.w = __expf(v.w);
            dst[k] = v;
        }
    }

    // ---- exp(trans): forward needs COLUMN cc (rows split by half),
    //      backward needs ROW cc (cols split by half) ----
    ull eF[17], eB[17];
    if (act) {
        #pragma unroll
        for (int k = 0; k < 16; k++) {
            int rr = h*32 + 2*k;
            eF[k] = pk2(__expf(__ldg(&trans[rr*TT + cc])),
                        __expf(__ldg(&trans[(rr+1)*TT + cc])));
            eB[k] = pk2(__expf(__ldg(&trans[cc*TT + rr])),
                        __expf(__ldg(&trans[cc*TT + rr + 1])));
        }
        eF[16] = (h == 0) ? pk2(__expf(__ldg(&trans[64*TT + cc])),
                                __expf(__ldg(&trans[65*TT + cc]))) : 0ULL;
        eB[16] = (h == 0) ? pk2(__expf(__ldg(&trans[cc*TT + 64])),
                                __expf(__ldg(&trans[cc*TT + 65]))) : 0ULL;
    } else {
        #pragma unroll
        for (int k = 0; k < 17; k++) { eF[k] = 0ULL; eB[k] = 0ULL; }
    }
    const float stq = act ? __expf(__ldg(&startT[cc])) : 0.f;
    const float eEn = act ? __expf(__ldg(&endT[cc]))   : 0.f;

    __syncthreads();   // esh ready

    // ---- init: alpha_0 = exp(start)*e_0 ; w_127 = e_127*exp(end) ----
    float rF = act ? (stq * esh[cc])            : 0.f;
    float rB = act ? (eEn * esh[127*TT + cc])   : 0.f;
    if (act && h == 0) { uF[loc] = rF; uW[loc] = rB; }
    {
        float mF = rF, mB = rB;
        #pragma unroll
        for (int o = 16; o; o >>= 1) {
            mF = fmaxf(mF, __shfl_xor_sync(~0u, mF, o));
            mB = fmaxf(mB, __shfl_xor_sync(~0u, mB, o));
        }
        if (lane == 0) { wmaxF[wid] = mF; wmaxB[wid] = mB; }
    }
    __syncthreads();
    float mF  = fmaxf(fmaxf(fmaxf(wmaxF[0], wmaxF[1]), fmaxf(wmaxF[2], wmaxF[3])), wmaxF[4]);
    float mB  = fmaxf(fmaxf(fmaxf(wmaxB[0], wmaxB[1]), fmaxf(wmaxB[2], wmaxB[3])), wmaxB[4]);
    float scF = __fdividef(1.0f, mF);
    float scB = __fdividef(1.0f, mB);
    float L   = __logf(mF) + __logf(mB);

    // ---- one interval: advance forward alpha AND backward w ----
    auto STEP2 = [&](int tf, int tb,
                     const float* ucf, float* unf,
                     const float* ucw, float* unw,
                     float sF, float sB, bool ren) {
        float emF = esh[tf*TT + cc];
        float emB = esh[tb*TT + cc];
        const ulonglong2* a2 = (const ulonglong2*)(ucf + h*36);
        const ulonglong2* b2 = (const ulonglong2*)(ucw + h*36);
        ull dF0 = 0, dF1 = 0, dB0 = 0, dB1 = 0;
        #pragma unroll
        for (int i = 0; i < 8; i++) {
            ulonglong2 va = a2[i];
            ulonglong2 vb = b2[i];
            fma2(dF0, va.x, eF[2*i]);   fma2(dB0, vb.x, eB[2*i]);
            fma2(dF1, va.y, eF[2*i+1]); fma2(dB1, vb.y, eB[2*i+1]);
        }
        fma2(dF0, *(const ull*)(ucf + 68), eF[16]);
        fma2(dB0, *(const ull*)(ucw + 68), eB[16]);
        add2(dF0, dF0, dF1);
        add2(dB0, dB0, dB1);
        float2 fA = upk2(dF0), fB = upk2(dB0);
        float vF = fA.x + fA.y;
        float vB = fB.x + fB.y;
        vF += __shfl_xor_sync(~0u, vF, 1);
        vB += __shfl_xor_sync(~0u, vB, 1);
        rF = act ? vF * (sF * emF) : 0.f;
        rB = act ? vB * (sB * emB) : 0.f;
        if (act && h == 0) { unf[loc] = rF; unw[loc] = rB; }
        if (ren) {
            float nF = rF, nB = rB;
            #pragma unroll
            for (int o = 16; o; o >>= 1) {
                nF = fmaxf(nF, __shfl_xor_sync(~0u, nF, o));
                nB = fmaxf(nB, __shfl_xor_sync(~0u, nB, o));
            }
            if (lane == 0) { wmaxF[wid] = nF; wmaxB[wid] = nB; }
        }
        __syncthreads();
    };

    // ---- main scan: 63 intervals (7 groups of 8 + final 7) ----
    float* ucF = uF; float* unF = uF + USTR;
    float* ucW = uW; float* unW = uW + USTR;
    int tf = 1, tb = 126;
    for (int g = 0; g < 8; g++) {
        const int n = (g == 7) ? 7 : 8;
        #pragma unroll 2
        for (int q = 0; q < n; q++) {
            STEP2(tf, tb, ucF, unF, ucW, unW,
                  (q == 0) ? scF : 1.0f, (q == 0) ? scB : 1.0f,
                  q == n-1);
            float* tp;
            tp = ucF; ucF = unF; unF = tp;
            tp = ucW; ucW = unW; unW = tp;
            tf++; tb--;
        }
        mF  = fmaxf(fmaxf(fmaxf(wmaxF[0], wmaxF[1]), fmaxf(wmaxF[2], wmaxF[3])), wmaxF[4]);
        mB  = fmaxf(fmaxf(fmaxf(wmaxB[0], wmaxB[1]), fmaxf(wmaxB[2], wmaxB[3])), wmaxB[4]);
        scF = __fdividef(1.0f, mF);
        scB = __fdividef(1.0f, mB);
        L  += __logf(mF) + __logf(mB);
    }
    // after loop: ucF holds alpha_63 (stored, pre-scF), rB = w_64[cc] (pre-scB)

    // ---- epilogue: Z = sum_j (M^T alpha_63)_j * w_64[j] (scales folded) ----
    {
        const ulonglong2* a2 = (const ulonglong2*)(ucF + h*36);
        ull dF0 = 0, dF1 = 0;
        #pragma unroll
        for (int i = 0; i < 8; i++) {
            ulonglong2 va = a2[i];
            fma2(dF0, va.x, eF[2*i]);
            fma2(dF1, va.y, eF[2*i+1]);
        }
        fma2(dF0, *(const ull*)(ucF + 68), eF[16]);
        add2(dF0, dF0, dF1);
        float2 fA = upk2(dF0);
        float vF = fA.x + fA.y;
        vF += __shfl_xor_sync(~0u, vF, 1);
        float contrib = 0.f;
        if (act && h == 0) contrib = (vF * scF) * (rB * scB);
        #pragma unroll
        for (int o = 16; o; o >>= 1) contrib += __shfl_xor_sync(~0u, contrib, o);
        if (lane == 0) sws[wid] = contrib;
    }
    __syncthreads();

    if (tid == 0) {
        float ws = (((sws[0] + sws[1]) + (sws[2] + sws[3])) + sws[4]);
        float gt = (((sgold[0] + sgold[1]) + (sgold[2] + sgold[3])) + sgold[4]);
        __stcg(&g_partial[seq], __logf(ws) + L - gt);
        __threadfence();
        unsigned c0 = atomicAdd(&g_count, 1u);
        *sflag = (c0 == NSEQ - 1) ? 1 : 0;
    }
    __syncthreads();

    // ---- fused final reduction in the last block ----
    if (*sflag) {
        float v = 0.f;
        if (tid < 128) v = __ldcg(&g_partial[tid]) + __ldcg(&g_partial[tid + 128]);
        #pragma unroll
        for (int o = 16; o; o >>= 1) v += __shfl_xor_sync(~0u, v, o);
        if (lane == 0) wred[wid] = v;
        __syncthreads();
        if (tid == 0) {
            out[0] = (((wred[0] + wred[1]) + (wred[2] + wred[3])) + wred[4])
                     * (1.0f / (float)NSEQ);
            g_count = 0;                       // reset for next graph replay
        }
    }
}

extern "C" void kernel_launch(void* const* d_in, const int* in_sizes, int n_in,
                              void* d_out, int out_size) {
    const float* score      = (const float*)d_in[0];
    const float* trans      = (const float*)d_in[1];
    const float* startT     = (const float*)d_in[2];
    const float* endT       = (const float*)d_in[3];
    const int*   v_label    = (const int*)d_in[4];
    const int*   role_label = (const int*)d_in[5];
    float* out = (float*)d_out;

    cudaFuncSetAttribute(crf_kernel,
                         cudaFuncAttributeMaxDynamicSharedMemorySize, SMEM_BYTES);

    crf_kernel<<<NSEQ, NTHR, SMEM_BYTES>>>(
        score, trans, startT, endT, v_label, role_label, out);
}

// round 9
// speedup vs baseline: 1.2691x; 1.0062x over previous
#include <cuda_runtime.h>
#include <math.h>

// Fixed shapes: B=32, S=128, V=8, T=66 -> 256 independent sequences.
// One block (128 thr) per sequence. Two independent 2-warp TEAMS:
//   team 0 (warps 0,1): forward  alpha_0 -> alpha_63   (63 steps)
//   team 1 (warps 2,3): backward w_127  -> w_64        (63 steps)
// Teams sync only on their own named barrier; meet once at the epilogue:
//   Z = alpha_63^T M w_64.
#define TT   66
#define SS   128
#define NSEQ 256
#define NTHR 128

typedef unsigned long long ull;

__device__ float        g_partial[NSEQ];
__device__ unsigned int g_count = 0;

static __device__ __forceinline__ ull pk2(float lo, float hi) {
    ull r; asm("mov.b64 %0, {%1,%2};" : "=l"(r) : "f"(lo), "f"(hi)); return r;
}
static __device__ __forceinline__ void fma2(ull& d, ull a, ull b) {
    asm("fma.rn.f32x2 %0, %1, %2, %0;" : "+l"(d) : "l"(a), "l"(b));
}
static __device__ __forceinline__ void add2(ull& d, ull a, ull b) {
    asm("add.rn.f32x2 %0, %1, %2;" : "=l"(d) : "l"(a), "l"(b));
}
static __device__ __forceinline__ float2 upk2(ull v) {
    float lo, hi; asm("mov.b64 {%0,%1}, %2;" : "=f"(lo), "=f"(hi) : "l"(v));
    return make_float2(lo, hi);
}
#define TEAM_BAR(tm) asm volatile("bar.sync %0, 64;" :: "r"((tm) + 1) : "memory")

__global__ void __launch_bounds__(NTHR) crf_kernel(
    const float* __restrict__ score,       // [B,S,S,T]
    const float* __restrict__ trans,       // [T,T]
    const float* __restrict__ startT,      // [T]
    const float* __restrict__ endT,        // [T]
    const int*   __restrict__ v_label,     // [B*V]
    const int*   __restrict__ role_label,  // [B*V][S]
    float*       __restrict__ out)
{
    __shared__ __align__(16) float ubuf[2][2][72];  // [team][pingpong][72], pads 66..71 = 0
    __shared__ float smax[2][2];                    // [team][warp-in-team]
    __shared__ float sL[2], sSc[2];
    __shared__ float sgold[4], sws[2], wred[4];
    __shared__ int   sflag;

    const int tid  = threadIdx.x;
    const int lane = tid & 31;
    const int wid  = tid >> 5;
    const int team = wid >> 1;             // 0 = forward, 1 = backward
    const int tw   = wid & 1;              // warp within team
    const int seq  = blockIdx.x;
    const int vr   = __ldg(&v_label[seq]);
    const float* erow = score + ((size_t)((seq >> 3)*SS + vr))*SS*TT;

    const int c   = 32*tw + lane;          // my state (column)
    const int xc  = 64 + tw;               // team-warp's extra state
    const int g   = lane & 3;              // redundancy group for extra state
    const int dir = team ? -1 : 1;

    // zero pads (floats 66..71 of all 4 slabs)
    if (tid < 24) {
        int s = tid / 6, p = tid - 6*s;
        ubuf[s >> 1][s & 1][66 + p] = 0.f;
    }

    // ---- gold path: one position per thread ----
    {
        int s  = tid;
        int tg = __ldg(&role_label[seq*SS + s]);
        float gg = __ldg(&erow[s*TT + tg]);
        if (s < SS-1) gg += __ldg(&trans[tg*TT + __ldg(&role_label[seq*SS + s + 1])]);
        else          gg += __ldg(&endT[tg]);
        if (s == 0)   gg += __ldg(&startT[tg]);
        #pragma unroll
        for (int o = 16; o; o >>= 1) gg += __shfl_xor_sync(~0u, gg, o);
        if (lane == 0) sgold[wid] = gg;
    }

    // ---- exp(trans) registers: forward = COLUMN c; backward = ROW c ----
    ull e2[34], ex[9];
    if (team == 0) {
        #pragma unroll
        for (int m = 0; m < 33; m++)
            e2[m] = pk2(__expf(__ldg(&trans[(2*m  )*TT + c])),
                        __expf(__ldg(&trans[(2*m+1)*TT + c])));
        #pragma unroll
        for (int q = 0; q < 8; q++) {
            int rr = 16*g + 2*q;
            ex[q] = pk2(__expf(__ldg(&trans[rr*TT + xc])),
                        __expf(__ldg(&trans[(rr+1)*TT + xc])));
        }
        ex[8] = (g == 0) ? pk2(__expf(__ldg(&trans[64*TT + xc])),
                               __expf(__ldg(&trans[65*TT + xc]))) : 0ULL;
    } else {
        #pragma unroll
        for (int m = 0; m < 33; m++)
            e2[m] = pk2(__expf(__ldg(&trans[c*TT + 2*m])),
                        __expf(__ldg(&trans[c*TT + 2*m + 1])));
        #pragma unroll
        for (int q = 0; q < 8; q++) {
            int rr = 16*g + 2*q;
            ex[q] = pk2(__expf(__ldg(&trans[xc*TT + rr])),
                        __expf(__ldg(&trans[xc*TT + rr + 1])));
        }
        ex[8] = (g == 0) ? pk2(__expf(__ldg(&trans[xc*TT + 64])),
                               __expf(__ldg(&trans[xc*TT + 65]))) : 0ULL;
    }

    // ---- init: alpha_0 = exp(start+e_0);  w_127 = exp(end+e_127) ----
    float r, rx;
    if (team == 0) {
        r  = __expf(__ldg(&startT[c])  + __ldg(&erow[c]));
        rx = __expf(__ldg(&startT[xc]) + __ldg(&erow[xc]));
    } else {
        r  = __expf(__ldg(&endT[c])  + __ldg(&erow[127*TT + c]));
        rx = __expf(__ldg(&endT[xc]) + __ldg(&erow[127*TT + xc]));
    }
    {
        float* u0 = ubuf[team][0];
        u0[c] = r;
        if (lane == 0) u0[xc] = rx;
        float mm = fmaxf(r, rx);
        #pragma unroll
        for (int o = 16; o; o >>= 1) mm = fmaxf(mm, __shfl_xor_sync(~0u, mm, o));
        if (lane == 0) smax[team][tw] = mm;
    }

    // ---- emission prefetch rings: slot k holds row t0 + dir*k ----
    const float* pt = erow + (team ? 126 : 1)*TT;    // row pointer for current step
    float emr[4], emx[4];
    #pragma unroll
    for (int k = 0; k < 4; k++) {
        emr[k] = __ldg(pt + dir*k*TT + c);
        emx[k] = __ldg(pt + dir*k*TT + xc);
    }

    TEAM_BAR(team);
    float m  = fmaxf(smax[team][0], smax[team][1]);
    float sc = __fdividef(1.0f, m);
    float L  = __logf(m);

    // ---- one step of the team's chain (R4-style body, named barrier) ----
    auto STEP = [&](int slot, bool refill, const float* uc, float* un,
                    float scale, bool renorm) {
        float em  = emr[slot];
        float emX = emx[slot];
        if (refill) {
            const float* rp = pt + 4*dir*TT;
            emr[slot] = __ldg(rp + c);
            emx[slot] = __ldg(rp + xc);
        }
        // extra state partial (group-redundant over 8 row-pairs + pair32)
        const ulonglong2* upx = (const ulonglong2*)(uc + 16*g);
        ulonglong2 a0 = upx[0], a1 = upx[1], a2 = upx[2], a3 = upx[3];
        ull a4 = *(const ull*)(uc + 64);
        ull x0 = 0, x1 = 0;
        fma2(x0, a0.x, ex[0]); fma2(x1, a0.y, ex[1]);
        fma2(x0, a1.x, ex[2]); fma2(x1, a1.y, ex[3]);
        fma2(x0, a2.x, ex[4]); fma2(x1, a2.y, ex[5]);
        fma2(x0, a3.x, ex[6]); fma2(x1, a3.y, ex[7]);
        fma2(x0, a4,   ex[8]);
        // main: full 66-dot for my state (broadcast loads)
        const ulonglong2* up = (const ulonglong2*)uc;
        ull d0 = 0, d1 = 0, d2 = 0, d3 = 0;
        #pragma unroll
        for (int i = 0; i < 17; i++) {
            ulonglong2 v = up[i];
            if (i & 1) { fma2(d2, v.x, e2[2*i]); fma2(d3, v.y, e2[2*i+1]); }
            else       { fma2(d0, v.x, e2[2*i]); fma2(d1, v.y, e2[2*i+1]); }
        }
        add2(x0, x0, x1);
        float2 xf = upk2(x0);
        float fx = xf.x + xf.y;
        fx += __shfl_xor_sync(~0u, fx, 1);
        fx += __shfl_xor_sync(~0u, fx, 2);
        add2(d0, d0, d2); add2(d1, d1, d3); add2(d0, d0, d1);
        float2 f = upk2(d0);
        r  = (f.x + f.y) * (scale * __expf(em));
        rx = fx          * (scale * __expf(emX));
        un[c] = r;
        if (lane == 0) un[xc] = rx;
        if (renorm) {
            float nn = fmaxf(r, rx);
            #pragma unroll
            for (int o = 16; o; o >>= 1) nn = fmaxf(nn, __shfl_xor_sync(~0u, nn, o));
            if (lane == 0) smax[team][tw] = nn;
        }
        TEAM_BAR(team);
        pt += dir*TT;
    };

    // ---- 63 steps: 7 groups of 8 + tail of 7; renorm at group ends ----
    float* uc = ubuf[team][0];
    float* un = ubuf[team][1];
    for (int grp = 0; grp < 7; grp++) {
        #pragma unroll
        for (int q = 0; q < 8; q++) {
            STEP(q & 3, true, uc, un, (q == 0) ? sc : 1.0f, q == 7);
            float* tp = uc; uc = un; un = tp;
        }
        m  = fmaxf(smax[team][0], smax[team][1]);
        sc = __fdividef(1.0f, m);
        L += __logf(m);
    }
    #pragma unroll
    for (int q = 0; q < 7; q++) {
        STEP(q & 3, q < 3, uc, un, (q == 0) ? sc : 1.0f, q == 6);
        float* tp = uc; uc = un; un = tp;
    }
    m  = fmaxf(smax[team][0], smax[team][1]);
    sc = __fdividef(1.0f, m);
    L += __logf(m);
    // invariant: actual = stored * exp(L) * sc  (sc pending, not yet applied)

    if (lane == 0 && tw == 0) { sL[team] = L; sSc[team] = sc; }
    __syncthreads();    // teams meet: both final buffers + sL/sSc visible

    // ---- epilogue (forward team): Z = sum_j (M^T alpha_63)_j * w_64[j] ----
    if (team == 0) {
        const float* ua = ubuf[0][1];    // alpha_63 (stored, pending sc)
        const float* uw = ubuf[1][1];    // w_64     (stored, pending sSc[1])
        const float scB = sSc[1];
        // extra states 64,65 of M^T alpha
        const ulonglong2* upx = (const ulonglong2*)(ua + 16*g);
        ulonglong2 a0 = upx[0], a1 = upx[1], a2 = upx[2], a3 = upx[3];
        ull a4 = *(const ull*)(ua + 64);
        ull x0 = 0, x1 = 0;
        fma2(x0, a0.x, ex[0]); fma2(x1, a0.y, ex[1]);
        fma2(x0, a1.x, ex[2]); fma2(x1, a1.y, ex[3]);
        fma2(x0, a2.x, ex[4]); fma2(x1, a2.y, ex[5]);
        fma2(x0, a3.x, ex[6]); fma2(x1, a3.y, ex[7]);
        fma2(x0, a4,   ex[8]);
        const ulonglong2* up = (const ulonglong2*)ua;
        ull d0 = 0, d1 = 0, d2 = 0, d3 = 0;
        #pragma unroll
        for (int i = 0; i < 17; i++) {
            ulonglong2 v = up[i];
            if (i & 1) { fma2(d2, v.x, e2[2*i]); fma2(d3, v.y, e2[2*i+1]); }
            else       { fma2(d0, v.x, e2[2*i]); fma2(d1, v.y, e2[2*i+1]); }
        }
        add2(x0, x0, x1);
        float2 xf = upk2(x0);
        float fx = xf.x + xf.y;
        fx += __shfl_xor_sync(~0u, fx, 1);
        fx += __shfl_xor_sync(~0u, fx, 2);
        add2(d0, d0, d2); add2(d1, d1, d3); add2(d0, d0, d1);
        float2 f = upk2(d0);
        float vF = f.x + f.y;
        float contrib = (vF * sc) * (uw[c] * scB);
        if (lane == 0) contrib += (fx * sc) * (uw[xc] * scB);
        #pragma unroll
        for (int o = 16; o; o >>= 1) contrib += __shfl_xor_sync(~0u, contrib, o);
        if (lane == 0) sws[tw] = contrib;
    }
    __syncthreads();

    if (tid == 0) {
        float ws = sws[0] + sws[1];
        float gt = (sgold[0] + sgold[1]) + (sgold[2] + sgold[3]);
        __stcg(&g_partial[seq], __logf(ws) + sL[0] + sL[1] - gt);
        __threadfence();
        unsigned c0 = atomicAdd(&g_count, 1u);
        sflag = (c0 == NSEQ - 1) ? 1 : 0;
    }
    __syncthreads();

    // ---- fused final reduction in the last block ----
    if (sflag) {
        float v = __ldcg(&g_partial[tid]) + __ldcg(&g_partial[tid + 128]);
        #pragma unroll
        for (int o = 16; o; o >>= 1) v += __shfl_xor_sync(~0u, v, o);
        if (lane == 0) wred[wid] = v;
        __syncthreads();
        if (tid == 0) {
            out[0] = ((wred[0] + wred[1]) + (wred[2] + wred[3])) * (1.0f / (float)NSEQ);
            g_count = 0;                   // reset for next graph replay
        }
    }
}

extern "C" void kernel_launch(void* const* d_in, const int* in_sizes, int n_in,
                              void* d_out, int out_size) {
    const float* score      = (const float*)d_in[0];
    const float* trans      = (const float*)d_in[1];
    const float* startT     = (const float*)d_in[2];
    const float* endT       = (const float*)d_in[3];
    const int*   v_label    = (const int*)d_in[4];
    const int*   role_label = (const int*)d_in[5];
    float* out = (float*)d_out;

    crf_kernel<<<NSEQ, NTHR>>>(score, trans, startT, endT, v_label, role_label, out);
}

// round 10
// speedup vs baseline: 1.5563x; 1.2263x over previous
#include <cuda_runtime.h>
#include <math.h>

// Fixed shapes: B=32, S=128, V=8, T=66 -> 256 independent sequences.
// One block (64 thr) per sequence, TWO independent warp-synchronous chains:
//   warp 0: forward  alpha_0 -> alpha_63   (63 steps, __syncwarp only)
//   warp 1: backward w_127  -> w_64        (63 steps, __syncwarp only)
// Meet once: Z = (alpha_63 M) . w_64. Serial depth 64 with ~280ns intervals.
#define TT   66
#define SS   128
#define NSEQ 256
#define NTHR 64
#define USTR 72          // u slab stride (floats), 16B-aligned

typedef unsigned long long ull;

__device__ float        g_partial[NSEQ];
__device__ unsigned int g_count = 0;

static __device__ __forceinline__ ull pk2(float lo, float hi) {
    ull r; asm("mov.b64 %0, {%1,%2};" : "=l"(r) : "f"(lo), "f"(hi)); return r;
}
static __device__ __forceinline__ void fma2(ull& d, ull a, ull b) {
    asm("fma.rn.f32x2 %0, %1, %2, %0;" : "+l"(d) : "l"(a), "l"(b));
}
static __device__ __forceinline__ void add2(ull& d, ull a, ull b) {
    asm("add.rn.f32x2 %0, %1, %2;" : "=l"(d) : "l"(a), "l"(b));
}
static __device__ __forceinline__ float2 upk2(ull v) {
    float lo, hi; asm("mov.b64 {%0,%1}, %2;" : "=f"(lo), "=f"(hi) : "l"(v));
    return make_float2(lo, hi);
}

__global__ void __launch_bounds__(NTHR) crf_kernel(
    const float* __restrict__ score,       // [B,S,S,T]
    const float* __restrict__ trans,       // [T,T]
    const float* __restrict__ startT,      // [T]
    const float* __restrict__ endT,        // [T]
    const int*   __restrict__ v_label,     // [B*V]
    const int*   __restrict__ role_label,  // [B*V][S]
    float*       __restrict__ out)
{
    __shared__ __align__(16) float esh[2][64*TT];   // [warp][its 64 rows][66] exp(emis)
    __shared__ __align__(16) float ubuf[2][2][USTR];// [warp][pingpong][72]
    __shared__ float sL[2], sSc[2], sgold[2], swsum[1], wred[2];
    __shared__ int   sflag;

    const int tid  = threadIdx.x;
    const int lane = tid & 31;
    const int w    = tid >> 5;             // 0 = forward, 1 = backward
    const int seq  = blockIdx.x;
    const int vr   = __ldg(&v_label[seq]);
    const float* erow = score + ((size_t)((seq >> 3)*SS + vr))*SS*TT;

    // ---- gold path: 2 positions per thread ----
    float gold = 0.f;
    #pragma unroll
    for (int p = 0; p < 2; p++) {
        int s  = tid + 64*p;
        int tg = __ldg(&role_label[seq*SS + s]);
        float gg = __ldg(&erow[s*TT + tg]);
        if (s < SS-1) gg += __ldg(&trans[tg*TT + __ldg(&role_label[seq*SS + s + 1])]);
        else          gg += __ldg(&endT[tg]);
        if (s == 0)   gg += __ldg(&startT[tg]);
        gold += gg;
    }
    #pragma unroll
    for (int o = 16; o; o >>= 1) gold += __shfl_xor_sync(~0u, gold, o);
    if (lane == 0) sgold[w] = gold;

    // ---- stage my warp's 64 emission rows, fused with exp ----
    {
        const float4* src = (const float4*)(erow + (w ? 64*TT : 0));
        float4*       dst = (float4*)esh[w];
        #pragma unroll 3
        for (int k = lane; k < (64*TT)/4; k += 32) {
            float4 v = __ldg(&src[k]);
            v.x = __expf(v.x); v.y = __expf(v.y);
            v.z = __expf(v.z); v.w = __expf(v.w);
            dst[k] = v;
        }
    }

    // ---- E registers (dual-interleave). Forward: columns (2l,2l+1) over rows.
    //      Backward: rows (2l,2l+1) over columns. Extra pair 64/65 likewise. ----
    ull eA[33], eB[33], xA[5], xB[5];
    const int g = lane & 7;
    if (w == 0) {
        #pragma unroll
        for (int m = 0; m < 33; m++) {
            float2 f0 = __ldg((const float2*)(trans + (2*m  )*TT) + lane);
            float2 f1 = __ldg((const float2*)(trans + (2*m+1)*TT) + lane);
            float a = __expf(f0.x), bq = __expf(f0.y);
            float c = __expf(f1.x), d  = __expf(f1.y);
            eA[m] = pk2(a, d);
            eB[m] = pk2(bq, c);
        }
        #pragma unroll
        for (int q = 0; q < 4; q++) {
            int rr = 2*(4*g + q);
            float2 h0 = __ldg((const float2*)(trans + rr*TT + 64));
            float2 h1 = __ldg((const float2*)(trans + (rr+1)*TT + 64));
            xA[q] = pk2(__expf(h0.x), __expf(h1.y));
            xB[q] = pk2(__expf(h0.y), __expf(h1.x));
        }
        if (g == 0) {
            float2 h0 = __ldg((const float2*)(trans + 64*TT + 64));
            float2 h1 = __ldg((const float2*)(trans + 65*TT + 64));
            xA[4] = pk2(__expf(h0.x), __expf(h1.y));
            xB[4] = pk2(__expf(h0.y), __expf(h1.x));
        } else { xA[4] = 0ULL; xB[4] = 0ULL; }
    } else {
        const float* row0 = trans + (2*lane    )*TT;
        const float* row1 = trans + (2*lane + 1)*TT;
        #pragma unroll
        for (int m = 0; m < 33; m++) {
            float2 f0 = __ldg((const float2*)row0 + m);   // (M[r0][2m], M[r0][2m+1])
            float2 f1 = __ldg((const float2*)row1 + m);   // (M[r1][2m], M[r1][2m+1])
            float a = __expf(f0.x), bq = __expf(f0.y);
            float c = __expf(f1.x), d  = __expf(f1.y);
            eA[m] = pk2(a, d);        // (M[r0][2m],  M[r1][2m+1])
            eB[m] = pk2(c, bq);       // (M[r1][2m],  M[r0][2m+1])
        }
        #pragma unroll
        for (int q = 0; q < 4; q++) {
            int rr = 2*(4*g + q);
            float2 h0 = __ldg((const float2*)(trans + 64*TT + rr));
            float2 h1 = __ldg((const float2*)(trans + 65*TT + rr));
            xA[q] = pk2(__expf(h0.x), __expf(h1.y));      // (M64[rr],  M65[rr+1])
            xB[q] = pk2(__expf(h1.x), __expf(h0.y));      // (M65[rr],  M64[rr+1])
        }
        if (g == 0) {
            float2 h0 = __ldg((const float2*)(trans + 64*TT + 64));
            float2 h1 = __ldg((const float2*)(trans + 65*TT + 64));
            xA[4] = pk2(__expf(h0.x), __expf(h1.y));
            xB[4] = pk2(__expf(h1.x), __expf(h0.y));
        } else { xA[4] = 0ULL; xB[4] = 0ULL; }
    }

    float2 bc = w ? __ldg((const float2*)endT + lane) : __ldg((const float2*)startT + lane);
    float2 bx = w ? __ldg((const float2*)(endT + 64)) : __ldg((const float2*)(startT + 64));

    __syncwarp();   // my esh half staged

    // ---- init: fwd alpha_0 = exp(start)*e_0 ; bwd w_127 = exp(end)*e_127 ----
    const float* e0 = esh[w] + (w ? 63*TT : 0);
    float r0   = __expf(bc.x) * e0[2*lane];
    float r1   = __expf(bc.y) * e0[2*lane + 1];
    float x64v = __expf(bx.x) * e0[64];
    float x65v = __expf(bx.y) * e0[65];
    float* uc = ubuf[w][0];
    float* un = ubuf[w][1];
    ((float2*)uc)[lane] = make_float2(r0, r1);
    if (lane == 0) *(float2*)(uc + 64) = make_float2(x64v, x65v);

    float m0 = fmaxf(fmaxf(r0, r1), fmaxf(x64v, x65v));
    #pragma unroll
    for (int o = 16; o; o >>= 1) m0 = fmaxf(m0, __shfl_xor_sync(~0u, m0, o));
    float sc = __fdividef(1.0f, m0);
    float L  = __logf(m0);
    __syncwarp();

    // ---- one step: identical body for both warps (direction in regs/pointer) ----
    const int dE = w ? -TT : TT;
    const float* emrow = esh[w] + (w ? 62*TT : TT);   // first step's emission row

    auto STEP = [&](float scale) {
        float2 em  = *((const float2*)emrow + lane);
        float2 emx = *(const float2*)(emrow + 64);
        ull dA0 = 0, dA1 = 0, dB0 = 0, dB1 = 0;
        const ulonglong2* up = (const ulonglong2*)uc;
        #pragma unroll
        for (int i = 0; i < 16; i++) {
            ulonglong2 va = up[i];
            fma2(dA0, va.x, eA[2*i]);   fma2(dB0, va.x, eB[2*i]);
            fma2(dA1, va.y, eA[2*i+1]); fma2(dB1, va.y, eB[2*i+1]);
        }
        ull last = *(const ull*)(uc + 64);
        fma2(dA0, last, eA[32]); fma2(dB0, last, eB[32]);
        // extra pair via group-redundant partials
        const ulonglong2* ux = (const ulonglong2*)(uc + 8*g);
        ulonglong2 va0 = ux[0], va1 = ux[1];
        ull XA = 0, XB = 0;
        fma2(XA, va0.x, xA[0]); fma2(XB, va0.x, xB[0]);
        fma2(XA, va0.y, xA[1]); fma2(XB, va0.y, xB[1]);
        fma2(XA, va1.x, xA[2]); fma2(XB, va1.x, xB[2]);
        fma2(XA, va1.y, xA[3]); fma2(XB, va1.y, xB[3]);
        fma2(XA, last,  xA[4]); fma2(XB, last,  xB[4]);
        float2 fa = upk2(XA), fb = upk2(XB);
        float px = fa.x + fb.y;
        float py = fa.y + fb.x;
        px += __shfl_xor_sync(~0u, px, 1);  py += __shfl_xor_sync(~0u, py, 1);
        px += __shfl_xor_sync(~0u, px, 2);  py += __shfl_xor_sync(~0u, py, 2);
        px += __shfl_xor_sync(~0u, px, 4);  py += __shfl_xor_sync(~0u, py, 4);
        add2(dA0, dA0, dA1); add2(dB0, dB0, dB1);
        float2 A = upk2(dA0), Bv = upk2(dB0);
        r0   = (A.x + Bv.y) * (scale * em.x);
        r1   = (A.y + Bv.x) * (scale * em.y);
        x64v = px * (scale * emx.x);
        x65v = py * (scale * emx.y);
        ((float2*)un)[lane] = make_float2(r0, r1);
        if (lane == 0) *(float2*)(un + 64) = make_float2(x64v, x65v);
        float* tp = uc; uc = un; un = tp;
        emrow += dE;
        __syncwarp();
    };

    // ---- 63 steps: groups of 8 (7 full + tail 7); renorm at every group end ----
    for (int grp = 0; grp < 8; grp++) {
        const int n = (grp == 7) ? 7 : 8;
        #pragma unroll 8
        for (int q = 0; q < n; q++) STEP((q == 0) ? sc : 1.0f);
        float mm = fmaxf(fmaxf(r0, r1), fmaxf(x64v, x65v));
        #pragma unroll
        for (int o = 16; o; o >>= 1) mm = fmaxf(mm, __shfl_xor_sync(~0u, mm, o));
        sc = __fdividef(1.0f, mm);
        L += __logf(mm);
    }
    // invariant: actual = stored * exp(L) * sc   (sc pending)

    if (lane == 0) { sL[w] = L; sSc[w] = sc; }
    __syncthreads();   // chains meet; both final slabs + scales visible

    // ---- epilogue (warp 0): Z = sum_j (alpha_63 M)[j] * w_64[j] ----
    if (w == 0) {
        const float* uw = ubuf[1][1];      // w_64 stored (63 steps end in slab 1)
        const float scB = sSc[1];
        // y = alpha_63 M (no emission), using forward E regs on own final slab
        ull dA0 = 0, dA1 = 0, dB0 = 0, dB1 = 0;
        const ulonglong2* up = (const ulonglong2*)uc;
        #pragma unroll
        for (int i = 0; i < 16; i++) {
            ulonglong2 va = up[i];
            fma2(dA0, va.x, eA[2*i]);   fma2(dB0, va.x, eB[2*i]);
            fma2(dA1, va.y, eA[2*i+1]); fma2(dB1, va.y, eB[2*i+1]);
        }
        ull last = *(const ull*)(uc + 64);
        fma2(dA0, last, eA[32]); fma2(dB0, last, eB[32]);
        const ulonglong2* ux = (const ulonglong2*)(uc + 8*g);
        ulonglong2 va0 = ux[0], va1 = ux[1];
        ull XA = 0, XB = 0;
        fma2(XA, va0.x, xA[0]); fma2(XB, va0.x, xB[0]);
        fma2(XA, va0.y, xA[1]); fma2(XB, va0.y, xB[1]);
        fma2(XA, va1.x, xA[2]); fma2(XB, va1.x, xB[2]);
        fma2(XA, va1.y, xA[3]); fma2(XB, va1.y, xB[3]);
        fma2(XA, last,  xA[4]); fma2(XB, last,  xB[4]);
        float2 fa = upk2(XA), fb = upk2(XB);
        float px = fa.x + fb.y;
        float py = fa.y + fb.x;
        px += __shfl_xor_sync(~0u, px, 1);  py += __shfl_xor_sync(~0u, py, 1);
        px += __shfl_xor_sync(~0u, px, 2);  py += __shfl_xor_sync(~0u, py, 2);
        px += __shfl_xor_sync(~0u, px, 4);  py += __shfl_xor_sync(~0u, py, 4);
        add2(dA0, dA0, dA1); add2(dB0, dB0, dB1);
        float2 A = upk2(dA0), Bv = upk2(dB0);
        float2 wv = ((const float2*)uw)[lane];
        float contrib = ((A.x + Bv.y)*sc) * (wv.x*scB)
                      + ((A.y + Bv.x)*sc) * (wv.y*scB);
        if (lane == 0) {
            float2 wx = *(const float2*)(uw + 64);
            contrib += (px*sc)*(wx.x*scB) + (py*sc)*(wx.y*scB);
        }
        #pragma unroll
        for (int o = 16; o; o >>= 1) contrib += __shfl_xor_sync(~0u, contrib, o);
        if (lane == 0) swsum[0] = contrib;
    }
    __syncthreads();

    if (tid == 0) {
        float logZ = __logf(swsum[0]) + sL[0] + sL[1];
        __stcg(&g_partial[seq], logZ - (sgold[0] + sgold[1]));
        __threadfence();
        unsigned c0 = atomicAdd(&g_count, 1u);
        sflag = (c0 == NSEQ - 1) ? 1 : 0;
    }
    __syncthreads();

    // ---- fused final reduction in the last block ----
    if (sflag) {
        float v = 0.f;
        #pragma unroll
        for (int p = 0; p < 4; p++) v += __ldcg(&g_partial[tid + 64*p]);
        #pragma unroll
        for (int o = 16; o; o >>= 1) v += __shfl_xor_sync(~0u, v, o);
        if (lane == 0) wred[w] = v;
        __syncthreads();
        if (tid == 0) {
            out[0] = (wred[0] + wred[1]) * (1.0f / (float)NSEQ);
            g_count = 0;                   // reset for next graph replay
        }
    }
}

extern "C" void kernel_launch(void* const* d_in, const int* in_sizes, int n_in,
                              void* d_out, int out_size) {
    const float* score      = (const float*)d_in[0];
    const float* trans      = (const float*)d_in[1];
    const float* startT     = (const float*)d_in[2];
    const float* endT       = (const float*)d_in[3];
    const int*   v_label    = (const int*)d_in[4];
    const int*   role_label = (const int*)d_in[5];
    float* out = (float*)d_out;

    crf_kernel<<<NSEQ, NTHR>>>(score, trans, startT, endT, v_label, role_label, out);
}